// round 5
// baseline (speedup 1.0000x reference)
#include <cuda_runtime.h>
#include <cstddef>

#define N_USERS 200000
#define N_ITEMS 100000
#define N_NODES (N_USERS + N_ITEMS)
#define N_EDGES 4800000
#define EMB     64
#define BATCH   4096
#define NBITW   ((N_NODES + 31) / 32)

// Scratch. Zero-initialized at module load; every launch leaves g_bits zeroed
// (k_out clears the words of all marked nodes) so replays start clean.
__device__ unsigned int g_bits[NBITW];                 // 37.5 KB node bitmask
__device__ __align__(16) float g_acc[(size_t)N_NODES * EMB];

// ---------------------------------------------------------------------------
// Kernel 1: mark needed nodes (atomicOr into bitmask) + zero their acc rows.
// 8 threads per output row, two float4 stores each (MLP=2 for TLB overlap).
// Duplicate ids are idempotent.
// ---------------------------------------------------------------------------
__global__ void k_mark(const int* __restrict__ uid, const int* __restrict__ iid) {
    int t = blockIdx.x * blockDim.x + threadIdx.x;
    if (t >= 2 * BATCH * 8) return;
    int row = t >> 3;
    int j   = t & 7;
    int node = (row < BATCH) ? uid[row] : (N_USERS + iid[row - BATCH]);
    if (j == 0) atomicOr(&g_bits[node >> 5], 1u << (node & 31));
    float4 z = make_float4(0.f, 0.f, 0.f, 0.f);
    float* base = &g_acc[(size_t)node * EMB];
    *reinterpret_cast<float4*>(base + 8 * j)     = z;
    *reinterpret_cast<float4*>(base + 8 * j + 4) = z;
}

// ---------------------------------------------------------------------------
// Kernel 2: edge scan. Each thread owns 4 consecutive edges (int4 load of
// adj_row), probes the L1-resident bitmask. Hit edges are processed
// warp-cooperatively, TWO per iteration: half-warp g handles hit g; each of
// its 16 lanes gathers a float4 of x0[col] and issues one float4 atomicAdd
// (RED.128) into acc[row].
// ---------------------------------------------------------------------------
__global__ void k_edges(const int*   __restrict__ arow,
                        const int*   __restrict__ acol,
                        const float* __restrict__ avals,
                        const float* __restrict__ uemb,
                        const float* __restrict__ iemb) {
    int t    = blockIdx.x * blockDim.x + threadIdx.x;
    int lane = threadIdx.x & 31;
    int g    = lane >> 4;           // half-warp id (0/1)
    int sl   = lane & 15;           // sub-lane within half-warp
    bool valid = (t * 4 < N_EDGES); // N_EDGES % 4 == 0

    int4 r4 = make_int4(0, 0, 0, 0);
    if (valid) r4 = reinterpret_cast<const int4*>(arow)[t];
    int rr[4] = {r4.x, r4.y, r4.z, r4.w};

    long base = (long)(t - lane);   // first thread of this warp

    #pragma unroll
    for (int j = 0; j < 4; ++j) {
        int  r   = rr[j];
        bool hit = valid && ((g_bits[r >> 5] >> (r & 31)) & 1u);
        unsigned m = __ballot_sync(0xffffffffu, hit);
        while (m) {
            int src0 = __ffs(m) - 1; m &= m - 1;
            int src1 = -1;
            if (m) { src1 = __ffs(m) - 1; m &= m - 1; }
            int src = g ? src1 : src0;
            // shfl must be warp-uniform-participating; src<0 handled by pred.
            int msrc = (src >= 0) ? src : src0;
            int row  = __shfl_sync(0xffffffffu, r, msrc);
            if (src >= 0) {
                long ee = 4L * (base + src) + j;
                int   c = __ldg(&acol[ee]);   // half-warp broadcast
                float v = __ldg(&avals[ee]);
                const float* x = (c < N_USERS)
                               ? (uemb + (size_t)c * EMB)
                               : (iemb + (size_t)(c - N_USERS) * EMB);
                float4 xv = *reinterpret_cast<const float4*>(x + 4 * sl);
                float4 mv = make_float4(v * xv.x, v * xv.y, v * xv.z, v * xv.w);
                atomicAdd(reinterpret_cast<float4*>(
                              &g_acc[(size_t)row * EMB + 4 * sl]), mv);
            }
        }
    }
}

// ---------------------------------------------------------------------------
// Kernel 3: output gather + bitmask cleanup.
// out[0:4096) = z1[user_id], out[4096:8192) = z1[N_USERS + item_id],
// z1 = 2*x0 + acc. 16 threads per row, one float4 each.
// j==0 thread clears the node's bit-word (leaves g_bits all-zero for the
// next launch; untouched words are already zero).
// ---------------------------------------------------------------------------
__global__ void k_out(const int*   __restrict__ uid,
                      const int*   __restrict__ iid,
                      const float* __restrict__ uemb,
                      const float* __restrict__ iemb,
                      float*       __restrict__ out) {
    int t = blockIdx.x * blockDim.x + threadIdx.x;
    if (t >= 2 * BATCH * 16) return;
    int row = t >> 4;
    int j   = t & 15;
    int node = (row < BATCH) ? uid[row] : (N_USERS + iid[row - BATCH]);
    if (j == 0) g_bits[node >> 5] = 0u;
    const float* x = (node < N_USERS)
                   ? (uemb + (size_t)node * EMB)
                   : (iemb + (size_t)(node - N_USERS) * EMB);
    float4 xv = *reinterpret_cast<const float4*>(x + 4 * j);
    float4 av = *reinterpret_cast<const float4*>(&g_acc[(size_t)node * EMB + 4 * j]);
    float4 o;
    o.x = 2.0f * xv.x + av.x;
    o.y = 2.0f * xv.y + av.y;
    o.z = 2.0f * xv.z + av.z;
    o.w = 2.0f * xv.w + av.w;
    *reinterpret_cast<float4*>(&out[(size_t)row * EMB + 4 * j]) = o;
}

// ---------------------------------------------------------------------------
extern "C" void kernel_launch(void* const* d_in, const int* in_sizes, int n_in,
                              void* d_out, int out_size) {
    const float* uemb  = (const float*)d_in[0];
    const float* iemb  = (const float*)d_in[1];
    const int*   arow  = (const int*)  d_in[2];
    const int*   acol  = (const int*)  d_in[3];
    const float* avals = (const float*)d_in[4];
    const int*   uid   = (const int*)  d_in[5];
    const int*   iid   = (const int*)  d_in[6];
    float*       out   = (float*)      d_out;

    {
        int n = 2 * BATCH * 8;                     // 65536
        k_mark<<<(n + 255) / 256, 256>>>(uid, iid);
    }
    {
        int n = N_EDGES / 4;                       // 1.2M threads
        k_edges<<<(n + 255) / 256, 256>>>(arow, acol, avals, uemb, iemb);
    }
    {
        int n = 2 * BATCH * 16;                    // 131072
        k_out<<<(n + 255) / 256, 256>>>(uid, iid, uemb, iemb, out);
    }
}